// round 4
// baseline (speedup 1.0000x reference)
#include <cuda_runtime.h>
#include <math.h>

// ---------------------------------------------------------------------------
// CfC / AutoNCP decoder:
//   B=512, T=128, I=512, layers n = {538, 358, 128}, in_tot = {1050, 896, 486}
//   per step, per layer:  xc = [input, h];
//     ff1 = tanh(xc W1m^T + b1); ff2 = tanh(xc W2m^T + b2)
//     t   = sigmoid(xc Wa^T + ba + xc Wb^T + bb)
//     h'  = ff1 + t*(ff2-ff1)
//   predictions = motor_outputs @ Wfc^T + bfc ; hn = concat(h_final)
// Output layout: d_out[0 : B*T*128) = predictions, d_out[B*T*128 : ) = hn
// ---------------------------------------------------------------------------

#define BB   512
#define TT   128
#define IDIM 512
#define OUTD 128

#define N0 538
#define N1 358
#define N2 128
#define K0 (IDIM + N0)   // 1050
#define K1 (N0 + N1)     // 896
#define K2 (N1 + N2)     // 486

#define WSZ0 (N0 * K0)   // 564900
#define WSZ1 (N1 * K1)   // 320768
#define WSZ2 (N2 * K2)   // 62208
#define WOFF1 (WSZ0)
#define WOFF2 (WSZ0 + WSZ1)
#define TOTW  (WSZ0 + WSZ1 + WSZ2)

#define OFFH0 0
#define OFFH1 (BB * N0)
#define OFFH2 (BB * (N0 + N1))
#define HTOT  (BB * 1024)

// Scratch (static device globals — no runtime allocation)
__device__ float gW1m[TOTW];
__device__ float gW2m[TOTW];
__device__ float gH[2][HTOT];

// ---------------------------------------------------------------------------
// Precompute masked weights: W1m = Wff1 * mask, W2m = Wff2 * mask (per layer)
// ---------------------------------------------------------------------------
__global__ void prep_kernel(const float* __restrict__ W1_0, const float* __restrict__ W2_0, const float* __restrict__ m0,
                            const float* __restrict__ W1_1, const float* __restrict__ W2_1, const float* __restrict__ m1,
                            const float* __restrict__ W1_2, const float* __restrict__ W2_2, const float* __restrict__ m2)
{
    for (int i = blockIdx.x * blockDim.x + threadIdx.x; i < TOTW; i += gridDim.x * blockDim.x) {
        const float *W1, *W2, *m;
        int j;
        if (i < WOFF1)      { W1 = W1_0; W2 = W2_0; m = m0; j = i; }
        else if (i < WOFF2) { W1 = W1_1; W2 = W2_1; m = m1; j = i - WOFF1; }
        else                { W1 = W1_2; W2 = W2_2; m = m2; j = i - WOFF2; }
        float mm = m[j];
        gW1m[i] = W1[j] * mm;
        gW2m[i] = W2[j] * mm;
    }
}

// h0 (B, 1024) -> per-layer contiguous state buffers in gH[0]
__global__ void init_h_kernel(const float* __restrict__ h0)
{
    for (int idx = blockIdx.x * blockDim.x + threadIdx.x; idx < HTOT; idx += gridDim.x * blockDim.x) {
        int b = idx >> 10;
        int c = idx & 1023;
        float v = h0[idx];
        if (c < N0)              gH[0][OFFH0 + b * N0 + c] = v;
        else if (c < N0 + N1)    gH[0][OFFH1 + b * N1 + (c - N0)] = v;
        else                     gH[0][OFFH2 + b * N2 + (c - N0 - N1)] = v;
    }
}

// final state buffers (gH[0] after 128 steps) -> hn (B, 1024)
__global__ void copy_hn_kernel(float* __restrict__ hn)
{
    for (int idx = blockIdx.x * blockDim.x + threadIdx.x; idx < HTOT; idx += gridDim.x * blockDim.x) {
        int b = idx >> 10;
        int c = idx & 1023;
        float v;
        if (c < N0)           v = gH[0][OFFH0 + b * N0 + c];
        else if (c < N0 + N1) v = gH[0][OFFH1 + b * N1 + (c - N0)];
        else                  v = gH[0][OFFH2 + b * N2 + (c - N0 - N1)];
        hn[idx] = v;
    }
}

// ---------------------------------------------------------------------------
// Fused CfC cell: 4 simultaneous GEMMs (shared A) + nonlinear epilogue.
//   BM = TM*8 rows of batch, BN = 32 output neurons, BK = 32, 256 threads.
//   Thread (rg = tid>>5, lk = tid&31) computes rows rg*TM..rg*TM+TM-1,
//   column lk of the tile, with 4 accumulators per element.
//   A-tile reads in compute are warp-broadcast; W-tile reads conflict-free.
//   Zero-padding of smem tiles handles ragged K and N tails (no tail loop).
// ---------------------------------------------------------------------------
template <int TM>
__global__ __launch_bounds__(256) void cell_kernel(
    const float* __restrict__ xin,   // non-null for layer 0 (x slice), else input = prev layer h
    int inA_off,                     // offset of prev-layer output inside gH[cur^1]
    int ldA,                         // row stride of input part
    int cur,                         // current state buffer parity
    int h_off,                       // offset of this layer's state in gH
    int w_off,                       // offset of this layer's masked weights
    const float* __restrict__ Wa, const float* __restrict__ Wb,
    const float* __restrict__ b1, const float* __restrict__ b2,
    const float* __restrict__ ba, const float* __restrict__ bb,
    int n, int in_dim,
    float* __restrict__ out2, int ld2)   // optional extra output (motor layer -> d_out)
{
    constexpr int BM = TM * 8;
    constexpr int BN = 32;
    constexpr int BK = 32;

    __shared__ float As[BK][BM + 4];        // [k][row], padded for fp32x4 reads
    __shared__ float Ws[4][BK][BN + 1];     // [mat][k][col]

    const int K = in_dim + n;
    const float* inA  = xin ? xin : (gH[cur ^ 1] + inA_off);
    const float* hcur = gH[cur] + h_off;
    float*       hout = gH[cur ^ 1] + h_off;
    const float* Wmats[4] = { gW1m + w_off, gW2m + w_off, Wa, Wb };

    const int tid = threadIdx.x;
    const int lk  = tid & 31;   // k index on load, column on compute
    const int rg  = tid >> 5;   // 0..7
    const int rowBase = blockIdx.y * BM;
    const int colBase = blockIdx.x * BN;

    float acc[TM][4];
#pragma unroll
    for (int m = 0; m < TM; m++)
#pragma unroll
        for (int w = 0; w < 4; w++) acc[m][w] = 0.f;

    for (int kt = 0; kt < K; kt += BK) {
        const int gk = kt + lk;
        const bool kin = (gk < K);

        // --- load A tile (coalesced along K) ---
#pragma unroll
        for (int i = 0; i < TM; i++) {
            int row = rg + i * 8;
            int gr  = rowBase + row;
            float v = 0.f;
            if (kin)
                v = (gk < in_dim) ? inA[gr * ldA + gk]
                                  : hcur[gr * n + (gk - in_dim)];
            As[lk][row] = v;
        }
        // --- load 4 weight tiles (coalesced along K) ---
#pragma unroll
        for (int w = 0; w < 4; w++) {
            const float* Wm = Wmats[w];
#pragma unroll
            for (int i = 0; i < 4; i++) {
                int wr = rg + i * 8;
                int gj = colBase + wr;
                float v = 0.f;
                if (kin && gj < n) v = Wm[gj * K + gk];
                Ws[w][lk][wr] = v;
            }
        }
        __syncthreads();

#pragma unroll
        for (int k = 0; k < BK; k++) {
            float a[TM];
            const float4* arow = reinterpret_cast<const float4*>(&As[k][rg * TM]);
#pragma unroll
            for (int m4 = 0; m4 < TM / 4; m4++) {
                float4 v4 = arow[m4];
                a[m4 * 4 + 0] = v4.x; a[m4 * 4 + 1] = v4.y;
                a[m4 * 4 + 2] = v4.z; a[m4 * 4 + 3] = v4.w;
            }
            float wv0 = Ws[0][k][lk];
            float wv1 = Ws[1][k][lk];
            float wv2 = Ws[2][k][lk];
            float wv3 = Ws[3][k][lk];
#pragma unroll
            for (int m = 0; m < TM; m++) {
                acc[m][0] += a[m] * wv0;
                acc[m][1] += a[m] * wv1;
                acc[m][2] += a[m] * wv2;
                acc[m][3] += a[m] * wv3;
            }
        }
        __syncthreads();
    }

    // --- fused CfC epilogue ---
    const int gj = colBase + lk;
    if (gj < n) {
        float vb1 = b1[gj], vb2 = b2[gj], vbs = ba[gj] + bb[gj];
#pragma unroll
        for (int m = 0; m < TM; m++) {
            int gr = rowBase + rg * TM + m;
            float f1 = tanhf(acc[m][0] + vb1);
            float f2 = tanhf(acc[m][1] + vb2);
            float s  = acc[m][2] + acc[m][3] + vbs;
            float ti = 1.f / (1.f + expf(-s));
            float hv = f1 + ti * (f2 - f1);
            hout[gr * n + gj] = hv;
            if (out2) out2[gr * ld2 + gj] = hv;
        }
    }
}

// ---------------------------------------------------------------------------
// Final FC, in-place on d_out predictions region: row block -> smem, then
// pred[m, j] = sum_k pred[m, k] * Wfc[j, k] + bfc[j].
// Each warp owns column j (uniform W loads), lanes own rows.
// ---------------------------------------------------------------------------
__global__ __launch_bounds__(256) void fc_kernel(float* __restrict__ pred,
                                                 const float* __restrict__ Wfc,
                                                 const float* __restrict__ bfc)
{
    __shared__ float As[64][129];   // pad 129: conflict-free row-varying reads
    const int tid  = threadIdx.x;
    const int lane = tid & 31;
    const int wrp  = tid >> 5;
    float* base = pred + (size_t)blockIdx.x * 64 * OUTD;

    for (int e = tid; e < 64 * OUTD; e += 256)
        As[e >> 7][e & 127] = base[e];
    __syncthreads();

    for (int jj = 0; jj < 16; jj++) {
        int j = jj * 8 + wrp;
        float acc0 = bfc[j], acc1 = bfc[j];
        const float* wr = Wfc + j * OUTD;
#pragma unroll 8
        for (int k = 0; k < OUTD; k++) {
            float wv = wr[k];                 // uniform across warp
            acc0 += As[lane][k] * wv;
            acc1 += As[lane + 32][k] * wv;
        }
        base[lane * OUTD + j]        = acc0;
        base[(lane + 32) * OUTD + j] = acc1;
    }
}

// ---------------------------------------------------------------------------
extern "C" void kernel_launch(void* const* d_in, const int* in_sizes, int n_in,
                              void* d_out, int out_size)
{
    const float* x    = (const float*)d_in[0];
    const float* h0   = (const float*)d_in[1];

    const float* mask0 = (const float*)d_in[2];
    const float* W1_0  = (const float*)d_in[3];
    const float* W2_0  = (const float*)d_in[4];
    const float* Wa_0  = (const float*)d_in[5];
    const float* Wb_0  = (const float*)d_in[6];
    const float* b1_0  = (const float*)d_in[7];
    const float* b2_0  = (const float*)d_in[8];
    const float* ba_0  = (const float*)d_in[9];
    const float* bb_0  = (const float*)d_in[10];

    const float* mask1 = (const float*)d_in[11];
    const float* W1_1  = (const float*)d_in[12];
    const float* W2_1  = (const float*)d_in[13];
    const float* Wa_1  = (const float*)d_in[14];
    const float* Wb_1  = (const float*)d_in[15];
    const float* b1_1  = (const float*)d_in[16];
    const float* b2_1  = (const float*)d_in[17];
    const float* ba_1  = (const float*)d_in[18];
    const float* bb_1  = (const float*)d_in[19];

    const float* mask2 = (const float*)d_in[20];
    const float* W1_2  = (const float*)d_in[21];
    const float* W2_2  = (const float*)d_in[22];
    const float* Wa_2  = (const float*)d_in[23];
    const float* Wb_2  = (const float*)d_in[24];
    const float* b1_2  = (const float*)d_in[25];
    const float* b2_2  = (const float*)d_in[26];
    const float* ba_2  = (const float*)d_in[27];
    const float* bb_2  = (const float*)d_in[28];

    const float* Wfc  = (const float*)d_in[29];
    const float* bfc  = (const float*)d_in[30];

    float* out = (float*)d_out;

    prep_kernel<<<1024, 256>>>(W1_0, W2_0, mask0, W1_1, W2_1, mask1, W1_2, W2_2, mask2);
    init_h_kernel<<<1024, 256>>>(h0);

    for (int t = 0; t < TT; t++) {
        const int cur = t & 1;
        // layer 0: input = x[:, t, :], BM=64 -> grid (17, 8) = 136 blocks
        cell_kernel<8><<<dim3(17, 8), 256>>>(x + (size_t)t * IDIM, 0, TT * IDIM,
                                             cur, OFFH0, 0,
                                             Wa_0, Wb_0, b1_0, b2_0, ba_0, bb_0,
                                             N0, IDIM, nullptr, 0);
        // layer 1: input = layer 0 new h, BM=32 -> grid (12, 16) = 192 blocks
        cell_kernel<4><<<dim3(12, 16), 256>>>(nullptr, OFFH0, N0,
                                              cur, OFFH1, WOFF1,
                                              Wa_1, Wb_1, b1_1, b2_1, ba_1, bb_1,
                                              N1, N0, nullptr, 0);
        // layer 2 (motor): also writes d_out[b, t, :]
        cell_kernel<4><<<dim3(4, 16), 256>>>(nullptr, OFFH1, N1,
                                             cur, OFFH2, WOFF2,
                                             Wa_2, Wb_2, b1_2, b2_2, ba_2, bb_2,
                                             N2, N1, out + (size_t)t * OUTD, TT * OUTD);
    }

    // predictions = motor @ Wfc^T + bfc (in place)
    fc_kernel<<<(BB * TT) / 64, 256>>>(out, Wfc, bfc);

    // hn tail, only if the harness expects both outputs
    if (out_size >= BB * TT * OUTD + BB * 1024)
        copy_hn_kernel<<<512, 256>>>(out + (size_t)BB * TT * OUTD);
}

// round 5
// speedup vs baseline: 1.6319x; 1.6319x over previous
#include <cuda_runtime.h>
#include <math.h>

// ---------------------------------------------------------------------------
// CfC / AutoNCP decoder:
//   B=512, T=128, I=512, layers n = {538, 358, 128}, in_tot = {1050, 896, 486}
//   per step, per layer:  xc = [input, h];
//     ff1 = tanh(xc W1m^T + b1); ff2 = tanh(xc W2m^T + b2)
//     t   = sigmoid(xc (Wa+Wb)^T + (ba+bb))          <-- folded: 3 GEMMs not 4
//     h'  = ff1 + t*(ff2-ff1)
//   predictions = motor_outputs @ Wfc^T + bfc ; hn = concat(h_final)
// ---------------------------------------------------------------------------

#define BB   512
#define TT   128
#define IDIM 512
#define OUTD 128

#define N0 538
#define N1 358
#define N2 128
#define K0 (IDIM + N0)   // 1050
#define K1 (N0 + N1)     // 896
#define K2 (N1 + N2)     // 486

#define WSZ0 (N0 * K0)
#define WSZ1 (N1 * K1)
#define WSZ2 (N2 * K2)
#define WOFF1 (WSZ0)
#define WOFF2 (WSZ0 + WSZ1)
#define TOTW  (WSZ0 + WSZ1 + WSZ2)

#define OFFH0 0
#define OFFH1 (BB * N0)
#define OFFH2 (BB * (N0 + N1))
#define HTOT  (BB * 1024)

// Scratch (static device globals — no runtime allocation)
__device__ float gW1m[TOTW];   // Wff1 * mask
__device__ float gW2m[TOTW];   // Wff2 * mask
__device__ float gWab[TOTW];   // Wta + Wtb
__device__ float gH[2][HTOT];

// ---------------------------------------------------------------------------
// Precompute: W1m = Wff1*mask, W2m = Wff2*mask, Wab = Wta + Wtb (per layer)
// ---------------------------------------------------------------------------
__global__ void prep_kernel(
    const float* __restrict__ W1_0, const float* __restrict__ W2_0,
    const float* __restrict__ Wa_0, const float* __restrict__ Wb_0, const float* __restrict__ m0,
    const float* __restrict__ W1_1, const float* __restrict__ W2_1,
    const float* __restrict__ Wa_1, const float* __restrict__ Wb_1, const float* __restrict__ m1,
    const float* __restrict__ W1_2, const float* __restrict__ W2_2,
    const float* __restrict__ Wa_2, const float* __restrict__ Wb_2, const float* __restrict__ m2)
{
    for (int i = blockIdx.x * blockDim.x + threadIdx.x; i < TOTW; i += gridDim.x * blockDim.x) {
        const float *W1, *W2, *Wa, *Wb, *m;
        int j;
        if (i < WOFF1)      { W1 = W1_0; W2 = W2_0; Wa = Wa_0; Wb = Wb_0; m = m0; j = i; }
        else if (i < WOFF2) { W1 = W1_1; W2 = W2_1; Wa = Wa_1; Wb = Wb_1; m = m1; j = i - WOFF1; }
        else                { W1 = W1_2; W2 = W2_2; Wa = Wa_2; Wb = Wb_2; m = m2; j = i - WOFF2; }
        float mm = m[j];
        gW1m[i] = W1[j] * mm;
        gW2m[i] = W2[j] * mm;
        gWab[i] = Wa[j] + Wb[j];
    }
}

// h0 (B, 1024) -> per-layer contiguous state buffers in gH[0]
__global__ void init_h_kernel(const float* __restrict__ h0)
{
    for (int idx = blockIdx.x * blockDim.x + threadIdx.x; idx < HTOT; idx += gridDim.x * blockDim.x) {
        int b = idx >> 10;
        int c = idx & 1023;
        float v = h0[idx];
        if (c < N0)              gH[0][OFFH0 + b * N0 + c] = v;
        else if (c < N0 + N1)    gH[0][OFFH1 + b * N1 + (c - N0)] = v;
        else                     gH[0][OFFH2 + b * N2 + (c - N0 - N1)] = v;
    }
}

// final state buffers (gH[0] after 128 steps) -> hn (B, 1024)
__global__ void copy_hn_kernel(float* __restrict__ hn)
{
    for (int idx = blockIdx.x * blockDim.x + threadIdx.x; idx < HTOT; idx += gridDim.x * blockDim.x) {
        int b = idx >> 10;
        int c = idx & 1023;
        float v;
        if (c < N0)           v = gH[0][OFFH0 + b * N0 + c];
        else if (c < N0 + N1) v = gH[0][OFFH1 + b * N1 + (c - N0)];
        else                  v = gH[0][OFFH2 + b * N2 + (c - N0 - N1)];
        hn[idx] = v;
    }
}

// ---------------------------------------------------------------------------
// Fused CfC cell: 3 simultaneous GEMMs (shared A) + nonlinear epilogue.
//   128 threads. BM = TM*4 batch rows, BN = 32 cols, BK = 32.
//   Compute mapping: lane = tid&31 owns column (colBase+lane); grp = tid>>5
//   owns rows grp*TM .. grp*TM+TM-1. 3*TM accumulators per thread.
//   Smem layouts (+1 pad) give conflict-free STS and LDS:
//     As[row][k]   -> compute reads are warp-broadcast (lane-uniform)
//     Ws[mat][k][c]-> compute reads consecutive in lane
//   Per k per thread: TM broadcast LDS + 3 LDS vs 3*TM FMA -> FMA-issue bound.
// ---------------------------------------------------------------------------
template <int TM>
__global__ __launch_bounds__(128) void cell_kernel(
    const float* __restrict__ xin,   // non-null for layer 0 (x slice)
    int inA_off,                     // offset of prev-layer output in gH[cur^1]
    int ldA,                         // row stride of input part
    int cur,                         // current state parity
    int h_off,                       // this layer's state offset in gH
    int w_off,                       // this layer's offset in gW* arrays
    const float* __restrict__ b1, const float* __restrict__ b2,
    const float* __restrict__ ba, const float* __restrict__ bb,
    int n, int in_dim,
    float* __restrict__ out2, int ld2)   // optional extra output (motor -> d_out)
{
    constexpr int BM = TM * 4;
    constexpr int BN = 32;
    constexpr int BK = 32;

    __shared__ float As[BM][BK + 1];
    __shared__ float Ws[3][BK][BN + 1];

    const int K = in_dim + n;
    const float* inA  = xin ? xin : (gH[cur ^ 1] + inA_off);
    const float* hcur = gH[cur] + h_off;
    float*       hout = gH[cur ^ 1] + h_off;
    const float* Wm[3] = { gW1m + w_off, gW2m + w_off, gWab + w_off };

    const int tid  = threadIdx.x;
    const int lane = tid & 31;    // load: k index ; compute: column
    const int grp  = tid >> 5;    // 0..3
    const int rowBase = blockIdx.y * BM;
    const int colBase = blockIdx.x * BN;

    float acc[TM][3];
#pragma unroll
    for (int m = 0; m < TM; m++)
#pragma unroll
        for (int w = 0; w < 3; w++) acc[m][w] = 0.f;

    for (int kt = 0; kt < K; kt += BK) {
        const int gk  = kt + lane;
        const bool kin = (gk < K);

        // --- A tile: rows grp*TM..grp*TM+TM-1, coalesced along k ---
#pragma unroll
        for (int i = 0; i < TM; i++) {
            int r  = grp * TM + i;
            int gr = rowBase + r;
            float v = 0.f;
            if (kin)
                v = (gk < in_dim) ? inA[gr * ldA + gk]
                                  : hcur[gr * n + (gk - in_dim)];
            As[r][lane] = v;
        }
        // --- 3 weight tiles: each thread loads 8 cols per mat, coalesced along k ---
#pragma unroll
        for (int w = 0; w < 3; w++) {
            const float* Wp = Wm[w];
#pragma unroll
            for (int i = 0; i < 8; i++) {
                int c  = grp * 8 + i;
                int gj = colBase + c;
                float v = 0.f;
                if (kin && gj < n) v = Wp[gj * K + gk];
                Ws[w][lane][c] = v;
            }
        }
        __syncthreads();

#pragma unroll 16
        for (int k = 0; k < BK; k++) {
            float a[TM];
#pragma unroll
            for (int i = 0; i < TM; i++) a[i] = As[grp * TM + i][k];   // broadcast
            float w0 = Ws[0][k][lane];
            float w1 = Ws[1][k][lane];
            float w2 = Ws[2][k][lane];
#pragma unroll
            for (int i = 0; i < TM; i++) {
                acc[i][0] += a[i] * w0;
                acc[i][1] += a[i] * w1;
                acc[i][2] += a[i] * w2;
            }
        }
        __syncthreads();
    }

    // --- fused CfC epilogue ---
    const int gj = colBase + lane;
    if (gj < n) {
        float vb1 = b1[gj], vb2 = b2[gj], vbs = ba[gj] + bb[gj];
#pragma unroll
        for (int i = 0; i < TM; i++) {
            int gr = rowBase + grp * TM + i;
            float f1 = tanhf(acc[i][0] + vb1);
            float f2 = tanhf(acc[i][1] + vb2);
            float ti = 1.f / (1.f + expf(-(acc[i][2] + vbs)));
            float hv = f1 + ti * (f2 - f1);
            hout[gr * n + gj] = hv;
            if (out2) out2[gr * ld2 + gj] = hv;
        }
    }
}

// ---------------------------------------------------------------------------
// Final FC, in-place on d_out predictions region.
// ---------------------------------------------------------------------------
__global__ __launch_bounds__(256) void fc_kernel(float* __restrict__ pred,
                                                 const float* __restrict__ Wfc,
                                                 const float* __restrict__ bfc)
{
    __shared__ float As[64][129];
    const int tid  = threadIdx.x;
    const int lane = tid & 31;
    const int wrp  = tid >> 5;
    float* base = pred + (size_t)blockIdx.x * 64 * OUTD;

    for (int e = tid; e < 64 * OUTD; e += 256)
        As[e >> 7][e & 127] = base[e];
    __syncthreads();

    for (int jj = 0; jj < 16; jj++) {
        int j = jj * 8 + wrp;
        float acc0 = bfc[j], acc1 = bfc[j];
        const float* wr = Wfc + j * OUTD;
#pragma unroll 8
        for (int k = 0; k < OUTD; k++) {
            float wv = wr[k];
            acc0 += As[lane][k] * wv;
            acc1 += As[lane + 32][k] * wv;
        }
        base[lane * OUTD + j]        = acc0;
        base[(lane + 32) * OUTD + j] = acc1;
    }
}

// ---------------------------------------------------------------------------
extern "C" void kernel_launch(void* const* d_in, const int* in_sizes, int n_in,
                              void* d_out, int out_size)
{
    const float* x    = (const float*)d_in[0];
    const float* h0   = (const float*)d_in[1];

    const float* mask0 = (const float*)d_in[2];
    const float* W1_0  = (const float*)d_in[3];
    const float* W2_0  = (const float*)d_in[4];
    const float* Wa_0  = (const float*)d_in[5];
    const float* Wb_0  = (const float*)d_in[6];
    const float* b1_0  = (const float*)d_in[7];
    const float* b2_0  = (const float*)d_in[8];
    const float* ba_0  = (const float*)d_in[9];
    const float* bb_0  = (const float*)d_in[10];

    const float* mask1 = (const float*)d_in[11];
    const float* W1_1  = (const float*)d_in[12];
    const float* W2_1  = (const float*)d_in[13];
    const float* Wa_1  = (const float*)d_in[14];
    const float* Wb_1  = (const float*)d_in[15];
    const float* b1_1  = (const float*)d_in[16];
    const float* b2_1  = (const float*)d_in[17];
    const float* ba_1  = (const float*)d_in[18];
    const float* bb_1  = (const float*)d_in[19];

    const float* mask2 = (const float*)d_in[20];
    const float* W1_2  = (const float*)d_in[21];
    const float* W2_2  = (const float*)d_in[22];
    const float* Wa_2  = (const float*)d_in[23];
    const float* Wb_2  = (const float*)d_in[24];
    const float* b1_2  = (const float*)d_in[25];
    const float* b2_2  = (const float*)d_in[26];
    const float* ba_2  = (const float*)d_in[27];
    const float* bb_2  = (const float*)d_in[28];

    const float* Wfc  = (const float*)d_in[29];
    const float* bfc  = (const float*)d_in[30];

    float* out = (float*)d_out;

    prep_kernel<<<1024, 256>>>(W1_0, W2_0, Wa_0, Wb_0, mask0,
                               W1_1, W2_1, Wa_1, Wb_1, mask1,
                               W1_2, W2_2, Wa_2, Wb_2, mask2);
    init_h_kernel<<<1024, 256>>>(h0);

    for (int t = 0; t < TT; t++) {
        const int cur = t & 1;
        // layer 0: input = x[:, t, :]  (BM=32, BN=32) -> grid (17, 16)
        cell_kernel<8><<<dim3(17, 16), 128>>>(x + (size_t)t * IDIM, 0, TT * IDIM,
                                              cur, OFFH0, 0,
                                              b1_0, b2_0, ba_0, bb_0,
                                              N0, IDIM, nullptr, 0);
        // layer 1: input = layer 0 new h -> grid (12, 16)
        cell_kernel<8><<<dim3(12, 16), 128>>>(nullptr, OFFH0, N0,
                                              cur, OFFH1, WOFF1,
                                              b1_1, b2_1, ba_1, bb_1,
                                              N1, N0, nullptr, 0);
        // layer 2 (motor): BM=16 -> grid (4, 32); also writes d_out[b, t, :]
        cell_kernel<4><<<dim3(4, 32), 128>>>(nullptr, OFFH1, N1,
                                             cur, OFFH2, WOFF2,
                                             b1_2, b2_2, ba_2, bb_2,
                                             N2, N1, out + (size_t)t * OUTD, TT * OUTD);
    }

    // predictions = motor @ Wfc^T + bfc (in place)
    fc_kernel<<<(BB * TT) / 64, 256>>>(out, Wfc, bfc);

    if (out_size >= BB * TT * OUTD + BB * 1024)
        copy_hn_kernel<<<512, 256>>>(out + (size_t)BB * TT * OUTD);
}

// round 6
// speedup vs baseline: 2.5439x; 1.5588x over previous
#include <cuda_runtime.h>
#include <math.h>
#include <stdint.h>

// ---------------------------------------------------------------------------
// CfC / AutoNCP decoder, wavefront-pipelined:
//   layer l at wavefront s computes t = s - l  (independent across layers)
//   one fused kernel per wavefront, blocks partitioned across the 3 layers.
//   Cell math per layer:
//     xc = [input, h];  ff1 = tanh(xc W1m^T + b1); ff2 = tanh(xc W2m^T + b2)
//     ti = sigmoid(xc (Wa+Wb)^T + (ba+bb));  h' = ff1 + ti*(ff2-ff1)
//   predictions = motor @ Wfc^T + bfc ; hn = concat(final h)
// ---------------------------------------------------------------------------

#define BB   512
#define TT   128
#define IDIM 512
#define OUTD 128

#define N0 538
#define N1 358
#define N2 128
#define K0 (IDIM + N0)   // 1050
#define K1 (N0 + N1)     // 896
#define K2 (N1 + N2)     // 486

#define WSZ0 (N0 * K0)
#define WSZ1 (N1 * K1)
#define WSZ2 (N2 * K2)
#define WOFF1 (WSZ0)
#define WOFF2 (WSZ0 + WSZ1)
#define TOTW  (WSZ0 + WSZ1 + WSZ2)

#define OFFH0 0
#define OFFH1 (BB * N0)
#define OFFH2 (BB * (N0 + N1))
#define HTOT  (BB * 1024)

// Block partition of the fused wavefront grid
#define BLK_L0 272            // 17 col-tiles x 16 row-tiles (BM=32)
#define BLK_L1 192            // 12 x 16 (BM=32)
#define BLK_L2 128            //  4 x 32 (BM=16)
#define BLK_TOT (BLK_L0 + BLK_L1 + BLK_L2)   // 592

// Scratch (static device globals — no runtime allocation)
__device__ float gW1m[TOTW];   // Wff1 * mask
__device__ float gW2m[TOTW];   // Wff2 * mask
__device__ float gWab[TOTW];   // Wta + Wtb
__device__ float gH[2][HTOT];  // wavefront-parity double buffer

// ---------------------------------------------------------------------------
__global__ void prep_kernel(
    const float* __restrict__ W1_0, const float* __restrict__ W2_0,
    const float* __restrict__ Wa_0, const float* __restrict__ Wb_0, const float* __restrict__ m0,
    const float* __restrict__ W1_1, const float* __restrict__ W2_1,
    const float* __restrict__ Wa_1, const float* __restrict__ Wb_1, const float* __restrict__ m1,
    const float* __restrict__ W1_2, const float* __restrict__ W2_2,
    const float* __restrict__ Wa_2, const float* __restrict__ Wb_2, const float* __restrict__ m2)
{
    for (int i = blockIdx.x * blockDim.x + threadIdx.x; i < TOTW; i += gridDim.x * blockDim.x) {
        const float *W1, *W2, *Wa, *Wb, *m;
        int j;
        if (i < WOFF1)      { W1 = W1_0; W2 = W2_0; Wa = Wa_0; Wb = Wb_0; m = m0; j = i; }
        else if (i < WOFF2) { W1 = W1_1; W2 = W2_1; Wa = Wa_1; Wb = Wb_1; m = m1; j = i - WOFF1; }
        else                { W1 = W1_2; W2 = W2_2; Wa = Wa_2; Wb = Wb_2; m = m2; j = i - WOFF2; }
        float mm = m[j];
        gW1m[i] = W1[j] * mm;
        gW2m[i] = W2[j] * mm;
        gWab[i] = Wa[j] + Wb[j];
    }
}

// h0 -> per-layer contiguous state, written to BOTH parities (first read per
// layer happens at wavefront s = l, parity (l-1)&1).
__global__ void init_h_kernel(const float* __restrict__ h0)
{
    for (int idx = blockIdx.x * blockDim.x + threadIdx.x; idx < HTOT; idx += gridDim.x * blockDim.x) {
        int b = idx >> 10;
        int c = idx & 1023;
        float v = h0[idx];
        int off;
        if (c < N0)           off = OFFH0 + b * N0 + c;
        else if (c < N0 + N1) off = OFFH1 + b * N1 + (c - N0);
        else                  off = OFFH2 + b * N2 + (c - N0 - N1);
        gH[0][off] = v;
        gH[1][off] = v;
    }
}

// final h: layer0 @ s=127 -> gH[1]; layer1 @ s=128 -> gH[0]; layer2 @ s=129 -> gH[1]
__global__ void copy_hn_kernel(float* __restrict__ hn)
{
    for (int idx = blockIdx.x * blockDim.x + threadIdx.x; idx < HTOT; idx += gridDim.x * blockDim.x) {
        int b = idx >> 10;
        int c = idx & 1023;
        float v;
        if (c < N0)           v = gH[1][OFFH0 + b * N0 + c];
        else if (c < N0 + N1) v = gH[0][OFFH1 + b * N1 + (c - N0)];
        else                  v = gH[1][OFFH2 + b * N2 + (c - N0 - N1)];
        hn[idx] = v;
    }
}

// ---------------------------------------------------------------------------
// cp.async helpers
// ---------------------------------------------------------------------------
__device__ __forceinline__ void cp4(void* dst_smem, const float* src, bool pred)
{
    uint32_t d = (uint32_t)__cvta_generic_to_shared(dst_smem);
    const float* s = pred ? src : (const float*)gW1m;   // safe address when masked
    int sz = pred ? 4 : 0;                               // 0 -> zero-fill 4 bytes
    asm volatile("cp.async.ca.shared.global [%0], [%1], 4, %2;\n"
                 :: "r"(d), "l"(s), "r"(sz) : "memory");
}
__device__ __forceinline__ void cp_commit() { asm volatile("cp.async.commit_group;\n" ::: "memory"); }
template <int N>
__device__ __forceinline__ void cp_wait() { asm volatile("cp.async.wait_group %0;\n" :: "n"(N) : "memory"); }

// ---------------------------------------------------------------------------
// Fused CfC cell body (templated per layer). 128 threads.
//   BN = 32 cols, BK = 32, BM = 4*TM rows.  lane = col, grp (0..3) = row group.
//   2-stage cp.async double-buffered K pipeline, 3 GEMMs share the A tile.
// ---------------------------------------------------------------------------
template <int L>
__device__ __forceinline__ void cell_body(
    int bidx, int t, int wp,
    const float* __restrict__ x,
    const float* __restrict__ b1, const float* __restrict__ b2,
    const float* __restrict__ ba, const float* __restrict__ bb,
    float* __restrict__ out,
    float (*As)[32][33], float (*Ws)[3][32][33])
{
    constexpr int n      = (L == 0) ? N0 : (L == 1) ? N1 : N2;
    constexpr int in_dim = (L == 0) ? IDIM : (L == 1) ? N0 : N1;
    constexpr int K      = in_dim + n;
    constexpr int COLT   = (L == 0) ? 17 : (L == 1) ? 12 : 4;
    constexpr int TM     = (L == 2) ? 4 : 8;
    constexpr int BM     = TM * 4;
    constexpr int NT     = (K + 31) / 32;
    constexpr int woff   = (L == 0) ? 0 : (L == 1) ? WOFF1 : WOFF2;
    constexpr int hoff   = (L == 0) ? OFFH0 : (L == 1) ? OFFH1 : OFFH2;
    constexpr int poff   = (L == 1) ? OFFH0 : OFFH2 ? ((L == 2) ? OFFH1 : 0) : 0;

    const float* prevbuf = gH[wp ^ 1];
    const float* inA = (L == 0) ? (x + (size_t)t * IDIM) : (prevbuf + poff);
    const int    ldA = (L == 0) ? (TT * IDIM) : in_dim;
    const float* hcur = prevbuf + hoff;
    float*       hout = gH[wp] + hoff;
    const float* Wm0 = gW1m + woff;
    const float* Wm1 = gW2m + woff;
    const float* Wm2 = gWab + woff;

    const int tid  = threadIdx.x;
    const int lane = tid & 31;
    const int grp  = tid >> 5;
    const int rowBase = (bidx / COLT) * BM;
    const int colBase = (bidx % COLT) * 32;

    float acc[TM][3];
#pragma unroll
    for (int m = 0; m < TM; m++)
#pragma unroll
        for (int w = 0; w < 3; w++) acc[m][w] = 0.f;

    // ---- tile issue: A rows grp*TM+i at k=lane; W cols grp*8+i at k=lane ----
    auto issue = [&](int kt, int st) {
        const int gk  = kt * 32 + lane;
        const bool kin = (gk < K);
        const bool inx = (gk < in_dim);
        const int hk = gk - in_dim;
#pragma unroll
        for (int i = 0; i < TM; i++) {
            int r  = grp * TM + i;
            int gr = rowBase + r;
            const float* src = inx ? (inA + (size_t)gr * ldA + gk)
                                   : (hcur + (size_t)gr * n + hk);
            cp4(&As[st][r][lane], src, kin);
        }
#pragma unroll
        for (int i = 0; i < 8; i++) {
            int c  = grp * 8 + i;
            int gj = colBase + c;
            bool p = kin && (gj < n);
            size_t o = (size_t)gj * K + gk;
            cp4(&Ws[st][0][lane][c], Wm0 + o, p);
            cp4(&Ws[st][1][lane][c], Wm1 + o, p);
            cp4(&Ws[st][2][lane][c], Wm2 + o, p);
        }
    };

    issue(0, 0);
    cp_commit();

    for (int kt = 0; kt < NT; kt++) {
        const int st = kt & 1;
        if (kt + 1 < NT) {
            issue(kt + 1, st ^ 1);
            cp_commit();
            cp_wait<1>();
        } else {
            cp_wait<0>();
        }
        __syncthreads();

#pragma unroll 8
        for (int k = 0; k < 32; k++) {
            float a[TM];
#pragma unroll
            for (int i = 0; i < TM; i++) a[i] = As[st][grp * TM + i][k];  // broadcast
            float w0 = Ws[st][0][k][lane];
            float w1 = Ws[st][1][k][lane];
            float w2 = Ws[st][2][k][lane];
#pragma unroll
            for (int i = 0; i < TM; i++) {
                acc[i][0] += a[i] * w0;
                acc[i][1] += a[i] * w1;
                acc[i][2] += a[i] * w2;
            }
        }
        __syncthreads();
    }

    // ---- fused CfC epilogue ----
    const int gj = colBase + lane;
    if (gj < n) {
        float vb1 = b1[gj], vb2 = b2[gj], vbs = ba[gj] + bb[gj];
#pragma unroll
        for (int i = 0; i < TM; i++) {
            int gr = rowBase + grp * TM + i;
            float f1 = tanhf(acc[i][0] + vb1);
            float f2 = tanhf(acc[i][1] + vb2);
            float ti = 1.f / (1.f + expf(-(acc[i][2] + vbs)));
            float hv = f1 + ti * (f2 - f1);
            hout[(size_t)gr * n + gj] = hv;
            if (L == 2) out[(size_t)gr * (TT * OUTD) + (size_t)t * OUTD + gj] = hv;
        }
    }
}

// ---------------------------------------------------------------------------
// One wavefront: layer l active when 0 <= s-l < 128.
// ---------------------------------------------------------------------------
__global__ __launch_bounds__(128, 4) void wave_kernel(
    int s, const float* __restrict__ x,
    const float* __restrict__ b1_0, const float* __restrict__ b2_0,
    const float* __restrict__ ba_0, const float* __restrict__ bb_0,
    const float* __restrict__ b1_1, const float* __restrict__ b2_1,
    const float* __restrict__ ba_1, const float* __restrict__ bb_1,
    const float* __restrict__ b1_2, const float* __restrict__ b2_2,
    const float* __restrict__ ba_2, const float* __restrict__ bb_2,
    float* __restrict__ out)
{
    __shared__ float As[2][32][33];
    __shared__ float Ws[2][3][32][33];

    const int bx = blockIdx.x;
    const int wp = s & 1;

    if (bx < BLK_L0) {
        if (s < TT)
            cell_body<0>(bx, s, wp, x, b1_0, b2_0, ba_0, bb_0, nullptr, As, Ws);
    } else if (bx < BLK_L0 + BLK_L1) {
        int t = s - 1;
        if (t >= 0 && t < TT)
            cell_body<1>(bx - BLK_L0, t, wp, x, b1_1, b2_1, ba_1, bb_1, nullptr, As, Ws);
    } else {
        int t = s - 2;
        if (t >= 0 && t < TT)
            cell_body<2>(bx - BLK_L0 - BLK_L1, t, wp, x, b1_2, b2_2, ba_2, bb_2, out, As, Ws);
    }
}

// ---------------------------------------------------------------------------
// Final FC, in-place on d_out predictions region.
// ---------------------------------------------------------------------------
__global__ __launch_bounds__(256) void fc_kernel(float* __restrict__ pred,
                                                 const float* __restrict__ Wfc,
                                                 const float* __restrict__ bfc)
{
    __shared__ float As[64][129];
    const int tid  = threadIdx.x;
    const int lane = tid & 31;
    const int wrp  = tid >> 5;
    float* base = pred + (size_t)blockIdx.x * 64 * OUTD;

    for (int e = tid; e < 64 * OUTD; e += 256)
        As[e >> 7][e & 127] = base[e];
    __syncthreads();

    for (int jj = 0; jj < 16; jj++) {
        int j = jj * 8 + wrp;
        float acc0 = bfc[j], acc1 = bfc[j];
        const float* wr = Wfc + j * OUTD;
#pragma unroll 8
        for (int k = 0; k < OUTD; k++) {
            float wv = wr[k];
            acc0 += As[lane][k] * wv;
            acc1 += As[lane + 32][k] * wv;
        }
        base[lane * OUTD + j]        = acc0;
        base[(lane + 32) * OUTD + j] = acc1;
    }
}

// ---------------------------------------------------------------------------
extern "C" void kernel_launch(void* const* d_in, const int* in_sizes, int n_in,
                              void* d_out, int out_size)
{
    const float* x    = (const float*)d_in[0];
    const float* h0   = (const float*)d_in[1];

    const float* mask0 = (const float*)d_in[2];
    const float* W1_0  = (const float*)d_in[3];
    const float* W2_0  = (const float*)d_in[4];
    const float* Wa_0  = (const float*)d_in[5];
    const float* Wb_0  = (const float*)d_in[6];
    const float* b1_0  = (const float*)d_in[7];
    const float* b2_0  = (const float*)d_in[8];
    const float* ba_0  = (const float*)d_in[9];
    const float* bb_0  = (const float*)d_in[10];

    const float* mask1 = (const float*)d_in[11];
    const float* W1_1  = (const float*)d_in[12];
    const float* W2_1  = (const float*)d_in[13];
    const float* Wa_1  = (const float*)d_in[14];
    const float* Wb_1  = (const float*)d_in[15];
    const float* b1_1  = (const float*)d_in[16];
    const float* b2_1  = (const float*)d_in[17];
    const float* ba_1  = (const float*)d_in[18];
    const float* bb_1  = (const float*)d_in[19];

    const float* mask2 = (const float*)d_in[20];
    const float* W1_2  = (const float*)d_in[21];
    const float* W2_2  = (const float*)d_in[22];
    const float* Wa_2  = (const float*)d_in[23];
    const float* Wb_2  = (const float*)d_in[24];
    const float* b1_2  = (const float*)d_in[25];
    const float* b2_2  = (const float*)d_in[26];
    const float* ba_2  = (const float*)d_in[27];
    const float* bb_2  = (const float*)d_in[28];

    const float* Wfc  = (const float*)d_in[29];
    const float* bfc  = (const float*)d_in[30];

    float* out = (float*)d_out;

    prep_kernel<<<1024, 256>>>(W1_0, W2_0, Wa_0, Wb_0, mask0,
                               W1_1, W2_1, Wa_1, Wb_1, mask1,
                               W1_2, W2_2, Wa_2, Wb_2, mask2);
    init_h_kernel<<<1024, 256>>>(h0);

    // Wavefront sweep: s = 0 .. 129 (layer l computes t = s - l)
    for (int s = 0; s < TT + 2; s++) {
        wave_kernel<<<BLK_TOT, 128>>>(s, x,
                                      b1_0, b2_0, ba_0, bb_0,
                                      b1_1, b2_1, ba_1, bb_1,
                                      b1_2, b2_2, ba_2, bb_2,
                                      out);
    }

    // predictions = motor @ Wfc^T + bfc (in place)
    fc_kernel<<<(BB * TT) / 64, 256>>>(out, Wfc, bfc);

    if (out_size >= BB * TT * OUTD + BB * 1024)
        copy_hn_kernel<<<512, 256>>>(out + (size_t)BB * TT * OUTD);
}